// round 12
// baseline (speedup 1.0000x reference)
#include <cuda_runtime.h>
#include <cuda_bf16.h>
#include <math.h>

#define BB   16
#define SSZ  1024
#define DDIM 512
#define PDIM 256            // packed pairs per row
#define BSN  (BB*SSZ)       // 16384 rows
#define NEGF (-1e30f)

// ---------------- scratch (device globals: allocation-free) ----------------
__device__ float    g_conv [BSN*DDIM];
__device__ float    g_res  [BSN*DDIM];
__device__ unsigned g_n1h[BSN*PDIM], g_n1l[BSN*PDIM];
__device__ unsigned g_dh [BSN*PDIM], g_dl [BSN*PDIM];
__device__ unsigned g_qh [BSN*PDIM], g_ql [BSN*PDIM];
__device__ unsigned g_kh [BSN*PDIM], g_kl [BSN*PDIM];
__device__ unsigned g_vh [BSN*PDIM], g_vl [BSN*PDIM];
__device__ unsigned g_ah [BSN*PDIM], g_al [BSN*PDIM];
__device__ unsigned g_wmh[DDIM*PDIM], g_wml[DDIM*PDIM];
__device__ unsigned g_wqh[DDIM*PDIM], g_wql[DDIM*PDIM];
__device__ unsigned g_wkh[DDIM*PDIM], g_wkl[DDIM*PDIM];
__device__ unsigned g_wvh[DDIM*PDIM], g_wvl[DDIM*PDIM];
__device__ unsigned g_woh[DDIM*PDIM], g_wol[DDIM*PDIM];

// ---------------- helpers ----------------------------------------------------
__device__ __forceinline__ unsigned short bfu(float x) {
    __nv_bfloat16 b = __float2bfloat16_rn(x);
    return *(unsigned short*)&b;
}
__device__ __forceinline__ float bff(unsigned short u) {
    __nv_bfloat16 b = *(__nv_bfloat16*)&u;
    return __bfloat162float(b);
}
__device__ __forceinline__ void hl2(float x0, float x1, unsigned& H, unsigned& L) {
    const unsigned short h0 = bfu(x0), h1 = bfu(x1);
    const unsigned short l0 = bfu(x0 - bff(h0)), l1 = bfu(x1 - bff(h1));
    H = (unsigned)h0 | ((unsigned)h1 << 16);
    L = (unsigned)l0 | ((unsigned)l1 << 16);
}
__device__ __forceinline__ void mma16(float* c, const unsigned* a, const unsigned* b) {
    asm volatile(
        "mma.sync.aligned.m16n8k16.row.col.f32.bf16.bf16.f32 "
        "{%0,%1,%2,%3}, {%4,%5,%6,%7}, {%8,%9}, {%0,%1,%2,%3};\n"
        : "+f"(c[0]), "+f"(c[1]), "+f"(c[2]), "+f"(c[3])
        : "r"(a[0]), "r"(a[1]), "r"(a[2]), "r"(a[3]), "r"(b[0]), "r"(b[1]));
}
__device__ __forceinline__ void ldsm_x4(unsigned& r0, unsigned& r1, unsigned& r2,
                                        unsigned& r3, unsigned addr) {
    asm volatile("ldmatrix.sync.aligned.m8n8.x4.shared.b16 {%0,%1,%2,%3}, [%4];"
        : "=r"(r0), "=r"(r1), "=r"(r2), "=r"(r3) : "r"(addr));
}
__device__ __forceinline__ void ldsm_x4t(unsigned& r0, unsigned& r1, unsigned& r2,
                                         unsigned& r3, unsigned addr) {
    asm volatile("ldmatrix.sync.aligned.m8n8.x4.trans.shared.b16 {%0,%1,%2,%3}, [%4];"
        : "=r"(r0), "=r"(r1), "=r"(r2), "=r"(r3) : "r"(addr));
}
__device__ __forceinline__ unsigned su32(const void* p) {
    return (unsigned)__cvta_generic_to_shared(p);
}
#define CP16(d, s) asm volatile("cp.async.cg.shared.global [%0], [%1], 16;\n" :: "r"(d), "l"(s))
#define CP_COMMIT()  asm volatile("cp.async.commit_group;\n")
#define CP_WAIT1()   asm volatile("cp.async.wait_group 1;\n")

// ---------------- kernel: fp32 -> packed bf16 (hi, lo) for 5 weights ---------
struct CvtTab { const float4* in[5]; uint2* oh[5]; uint2* ol[5]; };
__global__ __launch_bounds__(256) void k_cvt5(CvtTab tab, int n4)
{
    const int w = blockIdx.y;
    int i = blockIdx.x * 256 + threadIdx.x;
    if (i >= n4) return;
    float4 v = tab.in[w][i];
    unsigned h0, l0, h1, l1;
    hl2(v.x, v.y, h0, l0);
    hl2(v.z, v.w, h1, l1);
    tab.oh[w][i] = make_uint2(h0, h1);
    tab.ol[w][i] = make_uint2(l0, l1);
}

// ---------------- kernel 1: conv + pe + gelu + LN1 (packed hi/lo out) --------
__global__ __launch_bounds__(128) void k_embed(
    const float* __restrict__ ts, const float* __restrict__ cw,
    const float* __restrict__ cb, const float* __restrict__ pe,
    const float* __restrict__ g1, const float* __restrict__ b1,
    float* __restrict__ convo, unsigned* __restrict__ n1h, unsigned* __restrict__ n1l)
{
    const int bs = blockIdx.x;
    const int b = bs >> 10, s = bs & 1023;
    const int t = threadIdx.x;
    const int d0 = t << 2;
    const float* tp = ts + ((size_t)b << 12) + (s << 2);
    const float t0 = tp[0], t1 = tp[1], t2 = tp[2], t3 = tp[3];

    const float4 cb4 = *(const float4*)(cb + d0);
    const float4 pe4 = *(const float4*)(pe + ((size_t)s << 9) + d0);

    float cvv[4], act[4];
    float ls1 = 0.f, ls2 = 0.f;
#pragma unroll
    for (int j = 0; j < 4; j++) {
        const float4 w = *(const float4*)(cw + ((d0 + j) << 2));
        float c = fmaf(t0, w.x, fmaf(t1, w.y, fmaf(t2, w.z, t3 * w.w)));
        c += ((const float*)&cb4)[j] + ((const float*)&pe4)[j];
        cvv[j] = c;
        const float a = 0.5f * c * (1.0f + erff(c * 0.70710678118654752f));
        act[j] = a; ls1 += a; ls2 += a * a;
    }
    *(float4*)(convo + ((size_t)bs << 9) + d0) = make_float4(cvv[0], cvv[1], cvv[2], cvv[3]);

    __shared__ float sa[4], sb[4];
#pragma unroll
    for (int o = 16; o; o >>= 1) {
        ls1 += __shfl_down_sync(0xffffffffu, ls1, o);
        ls2 += __shfl_down_sync(0xffffffffu, ls2, o);
    }
    if ((t & 31) == 0) { sa[t >> 5] = ls1; sb[t >> 5] = ls2; }
    __syncthreads();
    const float S1 = sa[0] + sa[1] + sa[2] + sa[3];
    const float S2 = sb[0] + sb[1] + sb[2] + sb[3];
    const float mean = S1 * (1.0f / 512.0f);
    const float var  = (S2 - 512.0f * mean * mean) * (1.0f / 511.0f);  // ddof=1
    const float rstd = rsqrtf(var + 1e-5f);
    const float gg = g1[s], be = b1[s];

    float v[4];
#pragma unroll
    for (int j = 0; j < 4; j++) v[j] = gg * (act[j] - mean) * rstd + be;
    unsigned H0, L0, H1, L1;
    hl2(v[0], v[1], H0, L0);
    hl2(v[2], v[3], H1, L1);
    const size_t pr = ((size_t)bs << 8) + (t << 1);
    *(uint2*)(n1h + pr) = make_uint2(H0, H1);
    *(uint2*)(n1l + pr) = make_uint2(L0, L1);
}

// ---------------- BF16x3 GEMM-NT, ldmatrix + term-major MMA order ------------
// Per mt-pair: 8 MMAs of al*bh (distinct accs), then 8 of ah*bl, then 8 of
// ah*bh -> same-accumulator reuse distance 8 (breaks dependent HMMA chains).
#define SP2 12               // smem row stride in pairs (8 data + 4 pad)
#define GARR 1536            // words per array per stage (128*12)
#define GST  (4*GARR)        // 6144 words per stage
__global__ __launch_bounds__(256, 2) void bf16_gemm(
    const unsigned* __restrict__ Agh, const unsigned* __restrict__ Agl,
    const unsigned* __restrict__ B0h, const unsigned* __restrict__ B0l,
    const unsigned* __restrict__ B1h, const unsigned* __restrict__ B1l,
    const unsigned* __restrict__ B2h, const unsigned* __restrict__ B2l,
    unsigned* __restrict__ C0h, unsigned* __restrict__ C0l,
    unsigned* __restrict__ C1h, unsigned* __restrict__ C1l,
    unsigned* __restrict__ C2h, unsigned* __restrict__ C2l,
    float* __restrict__ Cf, int mode, const int* __restrict__ te,
    const float* __restrict__ aux1, const float* __restrict__ aux2)
{
    __shared__ unsigned gsm[2 * GST];            // 49152 B static

    const unsigned* Bgh = B0h; const unsigned* Bgl = B0l;
    unsigned* Ch = C0h; unsigned* Cl = C0l;
    float scale = 1.0f;
    if (mode == 4) {
        if (blockIdx.z == 1)      { Bgh = B1h; Bgl = B1l; Ch = C1h; Cl = C1l; }
        else if (blockIdx.z == 2) { Bgh = B2h; Bgl = B2l; Ch = C2h; Cl = C2l; }
        else                      { scale = 0.125f; }
    }

    const int t = threadIdx.x;
    const int row0 = blockIdx.y << 7, col0 = blockIdx.x << 7;
    const int lrow = t >> 1, lchunk = t & 1;
    const size_t aoff = ((size_t)(row0 + lrow) << 8) + (lchunk << 2);
    const size_t boff = ((size_t)(col0 + lrow) << 8) + (lchunk << 2);
    const unsigned cta = su32(gsm);
    const unsigned sbase = cta + (unsigned)((lrow * SP2 + (lchunk << 2)) << 2);

    const int warp = t >> 5, lane = t & 31;
    const int gid = lane >> 2, tig = lane & 3;
    const int wm = warp & 1, wn = warp >> 1;

    const int arowr = (wm << 6) + (lane & 15);
    const unsigned acolB = (unsigned)(lane & 16);
    const int browr = (wn << 5) + (lane & 7) + (((lane >> 4) & 1) << 3);
    const unsigned bcolB = (unsigned)(((lane >> 3) & 1) << 4);

    float acc[4][4][4];
#pragma unroll
    for (int mt = 0; mt < 4; mt++)
#pragma unroll
        for (int nt = 0; nt < 4; nt++)
#pragma unroll
            for (int r = 0; r < 4; r++) acc[mt][nt][r] = 0.f;

#define GLOAD(kt, st) do {                                   \
        const unsigned kc = (unsigned)(kt) << 3;             \
        const unsigned sd = sbase + (st) * (GST << 2);       \
        CP16(sd,                 Agh + aoff + kc);           \
        CP16(sd + (GARR << 2),   Agl + aoff + kc);           \
        CP16(sd + (2*GARR << 2), Bgh + boff + kc);           \
        CP16(sd + (3*GARR << 2), Bgl + boff + kc);           \
    } while (0)

    GLOAD(0, 0); CP_COMMIT();
    GLOAD(1, 1); CP_COMMIT();

    for (int kt = 0; kt < 32; kt++) {
        CP_WAIT1();
        __syncthreads();
        const unsigned stB = cta + (kt & 1) * (GST << 2);

        unsigned bh[4][2], bl[4][2];
#pragma unroll
        for (int ntp = 0; ntp < 2; ntp++) {
            const unsigned ba = stB +
                (((2*GARR) + (browr + (ntp << 4)) * SP2) << 2) + bcolB;
            ldsm_x4(bh[2*ntp][0], bh[2*ntp][1], bh[2*ntp+1][0], bh[2*ntp+1][1], ba);
            ldsm_x4(bl[2*ntp][0], bl[2*ntp][1], bl[2*ntp+1][0], bl[2*ntp+1][1],
                    ba + (GARR << 2));
        }
#pragma unroll
        for (int mp = 0; mp < 2; mp++) {
            unsigned ah[2][4], al[2][4];
#pragma unroll
            for (int mh = 0; mh < 2; mh++) {
                const unsigned aa = stB +
                    (((arowr + (((mp << 1) + mh) << 4)) * SP2) << 2) + acolB;
                ldsm_x4(ah[mh][0], ah[mh][1], ah[mh][2], ah[mh][3], aa);
                ldsm_x4(al[mh][0], al[mh][1], al[mh][2], al[mh][3], aa + (GARR << 2));
            }
            // term-major: 8 distinct accumulators per term group
#pragma unroll
            for (int mh = 0; mh < 2; mh++)
#pragma unroll
                for (int nt = 0; nt < 4; nt++)
                    mma16(acc[(mp << 1) + mh][nt], al[mh], bh[nt]);
#pragma unroll
            for (int mh = 0; mh < 2; mh++)
#pragma unroll
                for (int nt = 0; nt < 4; nt++)
                    mma16(acc[(mp << 1) + mh][nt], ah[mh], bl[nt]);
#pragma unroll
            for (int mh = 0; mh < 2; mh++)
#pragma unroll
                for (int nt = 0; nt < 4; nt++)
                    mma16(acc[(mp << 1) + mh][nt], ah[mh], bh[nt]);
        }
        __syncthreads();
        if (kt + 2 < 32) GLOAD(kt + 2, kt & 1);
        CP_COMMIT();
    }

    // ---- epilogue ----
    if (mode == 3) {
#pragma unroll
        for (int mt = 0; mt < 4; mt++) {
            const int r1 = row0 + (wm << 6) + (mt << 4) + gid;
            const int r2 = r1 + 8;
#pragma unroll
            for (int nt = 0; nt < 4; nt++) {
                const int c = col0 + (wn << 5) + (nt << 3) + (tig << 1);
                const float a0 = aux1[c], a1 = aux1[c + 1];
                float v0 = acc[mt][nt][0] + a0 + aux2[((size_t)r1 << 9) + c];
                float v1 = acc[mt][nt][1] + a1 + aux2[((size_t)r1 << 9) + c + 1];
                float v2 = acc[mt][nt][2] + a0 + aux2[((size_t)r2 << 9) + c];
                float v3 = acc[mt][nt][3] + a1 + aux2[((size_t)r2 << 9) + c + 1];
                *(float2*)(Cf + ((size_t)r1 << 9) + c) = make_float2(v0, v1);
                *(float2*)(Cf + ((size_t)r2 << 9) + c) = make_float2(v2, v3);
            }
        }
    } else {
        int e = 0;
        if (mode == 0) e = te[row0 >> 10];
#pragma unroll
        for (int mt = 0; mt < 4; mt++) {
            const int r1 = row0 + (wm << 6) + (mt << 4) + gid;
            const int r2 = r1 + 8;
#pragma unroll
            for (int nt = 0; nt < 4; nt++) {
                const int c = col0 + (wn << 5) + (nt << 3) + (tig << 1);
                float a0 = 0.f, a1 = 0.f;
                if (mode == 0) {
                    a0 = aux1[((size_t)e << 9) + c];
                    a1 = aux1[((size_t)e << 9) + c + 1];
                }
                const float v0 = acc[mt][nt][0] * scale + a0;
                const float v1 = acc[mt][nt][1] * scale + a1;
                const float v2 = acc[mt][nt][2] * scale + a0;
                const float v3 = acc[mt][nt][3] * scale + a1;
                unsigned H, L;
                const size_t i0p = ((size_t)r1 << 8) + (c >> 1);
                const size_t i1p = ((size_t)r2 << 8) + (c >> 1);
                hl2(v0, v1, H, L); Ch[i0p] = H; Cl[i0p] = L;
                hl2(v2, v3, H, L); Ch[i1p] = H; Cl[i1p] = L;
            }
        }
    }
}

// ---------------- FA2-style bf16x3 attention, term-major MMA order -----------
#define RS 36
#define STW 4608
__global__ __launch_bounds__(128, 2) void k_attn5(
    const unsigned* __restrict__ qh, const unsigned* __restrict__ ql,
    const unsigned* __restrict__ kh, const unsigned* __restrict__ kl,
    const unsigned* __restrict__ vh, const unsigned* __restrict__ vl,
    unsigned* __restrict__ aoh, unsigned* __restrict__ aol)
{
    __shared__ unsigned smw[2 * STW];

    const int jt = (gridDim.x - 1) - blockIdx.x;
    const int h = blockIdx.y, b = blockIdx.z;
    const int j0 = jt << 6;
    const int t = threadIdx.x, warp = t >> 5, lane = t & 31;
    const int gid = lane >> 2, tig = lane & 3;
    const size_t rowb = ((size_t)b << 10);
    const int coff2 = h << 5;
    const unsigned sbase = su32(smw);

    const int lrow = t >> 2;
    const int lsub = (t & 3) << 3;

#define LOADQV(i0_, st_) do {                                                   \
        const size_t g_ = ((rowb + (unsigned)(i0_) + lrow) << 8) + coff2 + lsub; \
        const unsigned s_ = sbase + (((st_) * STW + lrow * RS + lsub) << 2);     \
        CP16(s_,                  qh + g_);                                     \
        CP16(s_ + 16,             qh + g_ + 4);                                 \
        CP16(s_ + (1152 << 2),      ql + g_);                                   \
        CP16(s_ + (1152 << 2) + 16, ql + g_ + 4);                               \
        CP16(s_ + (2304 << 2),      vh + g_);                                   \
        CP16(s_ + (2304 << 2) + 16, vh + g_ + 4);                               \
        CP16(s_ + (3456 << 2),      vl + g_);                                   \
        CP16(s_ + (3456 << 2) + 16, vl + g_ + 4);                               \
    } while (0)

    const int ntiles = (jt << 1) + 2;

    LOADQV(0, 0); CP_COMMIT();
    if (ntiles > 1) LOADQV(32, 1);
    CP_COMMIT();

    const int krow = j0 + (warp << 4) + gid;
    const size_t kg0 = ((rowb + krow) << 8) + coff2;
    const size_t kg8 = ((rowb + krow + 8) << 8) + coff2;
    unsigned kfh[4][4], kfl[4][4];
#pragma unroll
    for (int ks = 0; ks < 4; ks++) {
        const int p = (ks << 3) + tig;
        kfh[ks][0] = kh[kg0 + p];     kfh[ks][1] = kh[kg8 + p];
        kfh[ks][2] = kh[kg0 + p + 4]; kfh[ks][3] = kh[kg8 + p + 4];
        kfl[ks][0] = kl[kg0 + p];     kfl[ks][1] = kl[kg8 + p];
        kfl[ks][2] = kl[kg0 + p + 4]; kfl[ks][3] = kl[kg8 + p + 4];
    }

    const int qrowrel = (lane & 7) + ((lane & 16) >> 1);
    const unsigned qcol = (lane & 8) >> 1;
    const int vrowrel = (lane & 7) + (lane & 8);
    const unsigned vcol = (lane & 16) >> 2;

    float m0 = NEGF, m1 = NEGF, l0 = 0.f, l1 = 0.f;
    float acc[8][4];
#pragma unroll
    for (int nb = 0; nb < 8; nb++)
#pragma unroll
        for (int r = 0; r < 4; r++) acc[nb][r] = 0.f;

    const int jr0 = j0 + (warp << 4) + gid, jr1 = jr0 + 8;

    for (int it = 0; it < ntiles; ++it) {
        CP_WAIT1();
        __syncthreads();
        const unsigned stw = (it & 1) * STW;

        float s[4][4];
#pragma unroll
        for (int nb = 0; nb < 4; nb++)
#pragma unroll
            for (int r = 0; r < 4; r++) s[nb][r] = 0.f;
#pragma unroll
        for (int ks = 0; ks < 4; ks++) {
            unsigned qbh[4][2], qbl[4][2];
#pragma unroll
            for (int nbp = 0; nbp < 2; nbp++) {
                const unsigned qa = sbase +
                    ((stw + ((nbp << 4) + qrowrel) * RS + (ks << 3) + qcol) << 2);
                unsigned q0, q1, q2, q3, w0, w1, w2, w3;
                ldsm_x4(q0, q1, q2, q3, qa);
                ldsm_x4(w0, w1, w2, w3, qa + (1152 << 2));
                qbh[2*nbp][0] = q0; qbh[2*nbp][1] = q1;
                qbh[2*nbp+1][0] = q2; qbh[2*nbp+1][1] = q3;
                qbl[2*nbp][0] = w0; qbl[2*nbp][1] = w1;
                qbl[2*nbp+1][0] = w2; qbl[2*nbp+1][1] = w3;
            }
            // term-major across the 4 score tiles (distance 4)
#pragma unroll
            for (int u = 0; u < 4; u++) mma16(s[u], kfl[ks], qbh[u]);
#pragma unroll
            for (int u = 0; u < 4; u++) mma16(s[u], kfh[ks], qbl[u]);
#pragma unroll
            for (int u = 0; u < 4; u++) mma16(s[u], kfh[ks], qbh[u]);
        }

        if (it >= ntiles - 2) {
            const int i0 = it << 5;
#pragma unroll
            for (int nb = 0; nb < 4; nb++) {
                const int c = i0 + (nb << 3) + (tig << 1);
                if (c     > jr0) s[nb][0] = NEGF;
                if (c + 1 > jr0) s[nb][1] = NEGF;
                if (c     > jr1) s[nb][2] = NEGF;
                if (c + 1 > jr1) s[nb][3] = NEGF;
            }
        }

        float mt0 = NEGF, mt1 = NEGF;
#pragma unroll
        for (int nb = 0; nb < 4; nb++) {
            mt0 = fmaxf(mt0, fmaxf(s[nb][0], s[nb][1]));
            mt1 = fmaxf(mt1, fmaxf(s[nb][2], s[nb][3]));
        }
        mt0 = fmaxf(mt0, __shfl_xor_sync(0xffffffffu, mt0, 1));
        mt0 = fmaxf(mt0, __shfl_xor_sync(0xffffffffu, mt0, 2));
        mt1 = fmaxf(mt1, __shfl_xor_sync(0xffffffffu, mt1, 1));
        mt1 = fmaxf(mt1, __shfl_xor_sync(0xffffffffu, mt1, 2));
        const float mn0 = fmaxf(m0, mt0), mn1 = fmaxf(m1, mt1);
        const float sc0 = __expf(m0 - mn0), sc1 = __expf(m1 - mn1);
        m0 = mn0; m1 = mn1;

        float rs0 = 0.f, rs1 = 0.f;
#pragma unroll
        for (int nb = 0; nb < 4; nb++) {
            s[nb][0] = __expf(s[nb][0] - mn0);
            s[nb][1] = __expf(s[nb][1] - mn0);
            s[nb][2] = __expf(s[nb][2] - mn1);
            s[nb][3] = __expf(s[nb][3] - mn1);
            rs0 += s[nb][0] + s[nb][1];
            rs1 += s[nb][2] + s[nb][3];
        }
        rs0 += __shfl_xor_sync(0xffffffffu, rs0, 1);
        rs0 += __shfl_xor_sync(0xffffffffu, rs0, 2);
        rs1 += __shfl_xor_sync(0xffffffffu, rs1, 1);
        rs1 += __shfl_xor_sync(0xffffffffu, rs1, 2);
        l0 = l0 * sc0 + rs0;
        l1 = l1 * sc1 + rs1;

#pragma unroll
        for (int nb = 0; nb < 8; nb++) {
            acc[nb][0] *= sc0; acc[nb][1] *= sc0;
            acc[nb][2] *= sc1; acc[nb][3] *= sc1;
        }

#pragma unroll
        for (int kk = 0; kk < 2; kk++) {
            unsigned pah[4], pal[4];
            hl2(s[2*kk][0],     s[2*kk][1],     pah[0], pal[0]);
            hl2(s[2*kk][2],     s[2*kk][3],     pah[1], pal[1]);
            hl2(s[2*kk + 1][0], s[2*kk + 1][1], pah[2], pal[2]);
            hl2(s[2*kk + 1][2], s[2*kk + 1][3], pah[3], pal[3]);
#pragma unroll
            for (int np = 0; np < 2; np++) {
                unsigned vbh[4][2], vbl[4][2];
#pragma unroll
                for (int h2 = 0; h2 < 2; h2++) {
                    const int nbp = (np << 1) + h2;
                    const unsigned va = sbase +
                        ((stw + 2304 + ((kk << 4) + vrowrel) * RS + (nbp << 3) + vcol) << 2);
                    unsigned v0, v1, v2, v3, w0, w1, w2, w3;
                    ldsm_x4t(v0, v1, v2, v3, va);
                    ldsm_x4t(w0, w1, w2, w3, va + (1152 << 2));
                    vbh[2*h2][0] = v0; vbh[2*h2][1] = v1;
                    vbh[2*h2+1][0] = v2; vbh[2*h2+1][1] = v3;
                    vbl[2*h2][0] = w0; vbl[2*h2][1] = w1;
                    vbl[2*h2+1][0] = w2; vbl[2*h2+1][1] = w3;
                }
                // term-major across 4 acc tiles (distance 4)
#pragma unroll
                for (int u = 0; u < 4; u++) mma16(acc[(np << 2) + u], pal, vbh[u]);
#pragma unroll
                for (int u = 0; u < 4; u++) mma16(acc[(np << 2) + u], pah, vbl[u]);
#pragma unroll
                for (int u = 0; u < 4; u++) mma16(acc[(np << 2) + u], pah, vbh[u]);
            }
        }

        __syncthreads();
        if (it + 2 < ntiles) LOADQV((it + 2) << 5, it & 1);
        CP_COMMIT();
    }

    const float rl0 = 1.0f / l0, rl1 = 1.0f / l1;
    const size_t o1 = ((rowb + jr0) << 8) + coff2;
    const size_t o2 = ((rowb + jr1) << 8) + coff2;
#pragma unroll
    for (int nb = 0; nb < 8; nb++) {
        const int pp = (nb << 2) + tig;
        unsigned H, L;
        hl2(acc[nb][0] * rl0, acc[nb][1] * rl0, H, L);
        aoh[o1 + pp] = H; aol[o1 + pp] = L;
        hl2(acc[nb][2] * rl1, acc[nb][3] * rl1, H, L);
        aoh[o2 + pp] = H; aol[o2 + pp] = L;
    }
#undef LOADQV
}

// ---------------- kernel 4: LN2 + coalesced transpose to (B,D,S) -------------
__global__ __launch_bounds__(256) void k_ln2t(
    const float* __restrict__ res, const float* __restrict__ g2,
    const float* __restrict__ b2, float* __restrict__ out)
{
    __shared__ float sm[16 * 513];
    __shared__ float smean[16], srstd[16];

    const int blk = blockIdx.x;
    const int b = blk >> 6, s0 = (blk & 63) << 4;
    const int t = threadIdx.x;

    for (int i = t; i < 2048; i += 256) {
        const int r = i >> 7, c4 = (i & 127) << 2;
        const float4 v = *(const float4*)(res + ((size_t)((b << 10) + s0 + r) << 9) + c4);
        float* d = sm + r * 513 + c4;
        d[0] = v.x; d[1] = v.y; d[2] = v.z; d[3] = v.w;
    }
    __syncthreads();

    {
        const int r = t >> 4, tr = t & 15;
        float s1 = 0.f, s2 = 0.f;
        for (int k = tr; k < 512; k += 16) {
            const float x = sm[r * 513 + k];
            s1 += x; s2 += x * x;
        }
#pragma unroll
        for (int o = 8; o; o >>= 1) {
            s1 += __shfl_down_sync(0xffffffffu, s1, o, 16);
            s2 += __shfl_down_sync(0xffffffffu, s2, o, 16);
        }
        if (tr == 0) {
            const float mean = s1 * (1.0f / 512.0f);
            const float var  = (s2 - 512.0f * mean * mean) * (1.0f / 511.0f);
            smean[r] = mean;
            srstd[r] = rsqrtf(var + 1e-5f);
        }
    }
    __syncthreads();

    const float gg = g2[s0 + (t & 15)], be = b2[s0 + (t & 15)];
    for (int i = t; i < 8192; i += 256) {
        const int d = i >> 4, si = i & 15;
        const float x = sm[si * 513 + d];
        out[((size_t)((b << 9) + d) << 10) + s0 + si] =
            gg * (x - smean[si]) * srstd[si] + be;
    }
}

// ---------------- launch -----------------------------------------------------
extern "C" void kernel_launch(void* const* d_in, const int* in_sizes, int n_in,
                              void* d_out, int out_size)
{
    const float* ts     = (const float*)d_in[0];
    const int*   te     = (const int*)  d_in[1];
    const float* conv_w = (const float*)d_in[2];
    const float* conv_b = (const float*)d_in[3];
    const float* pe     = (const float*)d_in[4];
    const float* ts_emb = (const float*)d_in[5];
    const float* g1     = (const float*)d_in[6];
    const float* b1     = (const float*)d_in[7];
    const float* Mw     = (const float*)d_in[8];
    const float* Wq     = (const float*)d_in[9];
    const float* Wk     = (const float*)d_in[10];
    const float* Wv     = (const float*)d_in[11];
    const float* Wo     = (const float*)d_in[12];
    const float* bo     = (const float*)d_in[13];
    const float* g2     = (const float*)d_in[14];
    const float* b2     = (const float*)d_in[15];
    float* out = (float*)d_out;

    float *pc, *pr;
    unsigned *n1h, *n1l, *dh, *dl, *pqh, *pql, *pkh, *pkl, *pvh, *pvl, *ah, *al;
    unsigned *wmh, *wml, *wqh, *wql, *wkh, *wkl, *wvh, *wvl, *woh, *wol;
    cudaGetSymbolAddress((void**)&pc,  g_conv);
    cudaGetSymbolAddress((void**)&pr,  g_res);
    cudaGetSymbolAddress((void**)&n1h, g_n1h); cudaGetSymbolAddress((void**)&n1l, g_n1l);
    cudaGetSymbolAddress((void**)&dh,  g_dh);  cudaGetSymbolAddress((void**)&dl,  g_dl);
    cudaGetSymbolAddress((void**)&pqh, g_qh);  cudaGetSymbolAddress((void**)&pql, g_ql);
    cudaGetSymbolAddress((void**)&pkh, g_kh);  cudaGetSymbolAddress((void**)&pkl, g_kl);
    cudaGetSymbolAddress((void**)&pvh, g_vh);  cudaGetSymbolAddress((void**)&pvl, g_vl);
    cudaGetSymbolAddress((void**)&ah,  g_ah);  cudaGetSymbolAddress((void**)&al,  g_al);
    cudaGetSymbolAddress((void**)&wmh, g_wmh); cudaGetSymbolAddress((void**)&wml, g_wml);
    cudaGetSymbolAddress((void**)&wqh, g_wqh); cudaGetSymbolAddress((void**)&wql, g_wql);
    cudaGetSymbolAddress((void**)&wkh, g_wkh); cudaGetSymbolAddress((void**)&wkl, g_wkl);
    cudaGetSymbolAddress((void**)&wvh, g_wvh); cudaGetSymbolAddress((void**)&wvl, g_wvl);
    cudaGetSymbolAddress((void**)&woh, g_woh); cudaGetSymbolAddress((void**)&wol, g_wol);

    // weight packing (once per launch)
    const int n4 = DDIM * DDIM / 4;
    CvtTab tab;
    tab.in[0] = (const float4*)Mw; tab.oh[0] = (uint2*)wmh; tab.ol[0] = (uint2*)wml;
    tab.in[1] = (const float4*)Wq; tab.oh[1] = (uint2*)wqh; tab.ol[1] = (uint2*)wql;
    tab.in[2] = (const float4*)Wk; tab.oh[2] = (uint2*)wkh; tab.ol[2] = (uint2*)wkl;
    tab.in[3] = (const float4*)Wv; tab.oh[3] = (uint2*)wvh; tab.ol[3] = (uint2*)wvl;
    tab.in[4] = (const float4*)Wo; tab.oh[4] = (uint2*)woh; tab.ol[4] = (uint2*)wol;
    k_cvt5<<<dim3(n4 / 256, 5), 256>>>(tab, n4);

    k_embed<<<BSN, 128>>>(ts, conv_w, conv_b, pe, g1, b1, pc, n1h, n1l);

    dim3 gg(4, 128, 1);
    bf16_gemm<<<gg, 256>>>(n1h, n1l, wmh, wml, nullptr, nullptr, nullptr, nullptr,
                           dh, dl, nullptr, nullptr, nullptr, nullptr,
                           nullptr, 0, te, ts_emb, nullptr);
    dim3 gq(4, 128, 3);
    bf16_gemm<<<gq, 256>>>(dh, dl, wqh, wql, wkh, wkl, wvh, wvl,
                           pqh, pql, pkh, pkl, pvh, pvl,
                           nullptr, 4, nullptr, nullptr, nullptr);

    k_attn5<<<dim3(SSZ / 64, 8, BB), 128>>>(pqh, pql, pkh, pkl, pvh, pvl, ah, al);

    bf16_gemm<<<gg, 256>>>(ah, al, woh, wol, nullptr, nullptr, nullptr, nullptr,
                           nullptr, nullptr, nullptr, nullptr, nullptr, nullptr,
                           pr, 3, nullptr, bo, pc);

    k_ln2t<<<BB * 64, 256>>>(pr, g2, b2, out);
}

// round 13
// speedup vs baseline: 2.0090x; 2.0090x over previous
#include <cuda_runtime.h>
#include <cuda_fp16.h>
#include <math.h>

#define BB   16
#define SSZ  1024
#define DDIM 512
#define PDIM 256            // packed fp16 pairs per row
#define BSN  (BB*SSZ)       // 16384 rows
#define NEGF (-1e30f)

// ---------------- scratch (device globals: allocation-free) ----------------
__device__ float    g_conv[BSN*DDIM];
__device__ float    g_res [BSN*DDIM];
__device__ unsigned g_n1[BSN*PDIM];
__device__ unsigned g_d [BSN*PDIM];
__device__ unsigned g_q [BSN*PDIM];
__device__ unsigned g_k [BSN*PDIM];
__device__ unsigned g_v [BSN*PDIM];
__device__ unsigned g_a [BSN*PDIM];
__device__ unsigned g_wm[DDIM*PDIM];
__device__ unsigned g_wq[DDIM*PDIM];
__device__ unsigned g_wk[DDIM*PDIM];
__device__ unsigned g_wv[DDIM*PDIM];
__device__ unsigned g_wo[DDIM*PDIM];

// ---------------- helpers ----------------------------------------------------
__device__ __forceinline__ unsigned h2pk(float x0, float x1) {
    __half2 h = __floats2half2_rn(x0, x1);
    return *(unsigned*)&h;
}
__device__ __forceinline__ void mma16(float* c, const unsigned* a, const unsigned* b) {
    asm volatile(
        "mma.sync.aligned.m16n8k16.row.col.f32.f16.f16.f32 "
        "{%0,%1,%2,%3}, {%4,%5,%6,%7}, {%8,%9}, {%0,%1,%2,%3};\n"
        : "+f"(c[0]), "+f"(c[1]), "+f"(c[2]), "+f"(c[3])
        : "r"(a[0]), "r"(a[1]), "r"(a[2]), "r"(a[3]), "r"(b[0]), "r"(b[1]));
}
__device__ __forceinline__ void ldsm_x4(unsigned& r0, unsigned& r1, unsigned& r2,
                                        unsigned& r3, unsigned addr) {
    asm volatile("ldmatrix.sync.aligned.m8n8.x4.shared.b16 {%0,%1,%2,%3}, [%4];"
        : "=r"(r0), "=r"(r1), "=r"(r2), "=r"(r3) : "r"(addr));
}
__device__ __forceinline__ void ldsm_x4t(unsigned& r0, unsigned& r1, unsigned& r2,
                                         unsigned& r3, unsigned addr) {
    asm volatile("ldmatrix.sync.aligned.m8n8.x4.trans.shared.b16 {%0,%1,%2,%3}, [%4];"
        : "=r"(r0), "=r"(r1), "=r"(r2), "=r"(r3) : "r"(addr));
}
__device__ __forceinline__ unsigned su32(const void* p) {
    return (unsigned)__cvta_generic_to_shared(p);
}
#define CP16(d, s) asm volatile("cp.async.cg.shared.global [%0], [%1], 16;\n" :: "r"(d), "l"(s))
#define CP_COMMIT()  asm volatile("cp.async.commit_group;\n")
#define CP_WAIT1()   asm volatile("cp.async.wait_group 1;\n")

// ---------------- kernel: fp32 -> packed fp16 for 5 weights ------------------
struct CvtTab { const float4* in[5]; uint2* o[5]; };
__global__ __launch_bounds__(256) void k_cvt5(CvtTab tab, int n4)
{
    const int w = blockIdx.y;
    int i = blockIdx.x * 256 + threadIdx.x;
    if (i >= n4) return;
    float4 v = tab.in[w][i];
    tab.o[w][i] = make_uint2(h2pk(v.x, v.y), h2pk(v.z, v.w));
}

// ---------------- kernel 1: conv + pe + gelu + LN1 (packed fp16 out) ---------
__global__ __launch_bounds__(128) void k_embed(
    const float* __restrict__ ts, const float* __restrict__ cw,
    const float* __restrict__ cb, const float* __restrict__ pe,
    const float* __restrict__ g1, const float* __restrict__ b1,
    float* __restrict__ convo, unsigned* __restrict__ n1o)
{
    const int bs = blockIdx.x;
    const int b = bs >> 10, s = bs & 1023;
    const int t = threadIdx.x;
    const int d0 = t << 2;
    const float* tp = ts + ((size_t)b << 12) + (s << 2);
    const float t0 = tp[0], t1 = tp[1], t2 = tp[2], t3 = tp[3];

    const float4 cb4 = *(const float4*)(cb + d0);
    const float4 pe4 = *(const float4*)(pe + ((size_t)s << 9) + d0);

    float cvv[4], act[4];
    float ls1 = 0.f, ls2 = 0.f;
#pragma unroll
    for (int j = 0; j < 4; j++) {
        const float4 w = *(const float4*)(cw + ((d0 + j) << 2));
        float c = fmaf(t0, w.x, fmaf(t1, w.y, fmaf(t2, w.z, t3 * w.w)));
        c += ((const float*)&cb4)[j] + ((const float*)&pe4)[j];
        cvv[j] = c;
        const float a = 0.5f * c * (1.0f + erff(c * 0.70710678118654752f));
        act[j] = a; ls1 += a; ls2 += a * a;
    }
    *(float4*)(convo + ((size_t)bs << 9) + d0) = make_float4(cvv[0], cvv[1], cvv[2], cvv[3]);

    __shared__ float sa[4], sb[4];
#pragma unroll
    for (int o = 16; o; o >>= 1) {
        ls1 += __shfl_down_sync(0xffffffffu, ls1, o);
        ls2 += __shfl_down_sync(0xffffffffu, ls2, o);
    }
    if ((t & 31) == 0) { sa[t >> 5] = ls1; sb[t >> 5] = ls2; }
    __syncthreads();
    const float S1 = sa[0] + sa[1] + sa[2] + sa[3];
    const float S2 = sb[0] + sb[1] + sb[2] + sb[3];
    const float mean = S1 * (1.0f / 512.0f);
    const float var  = (S2 - 512.0f * mean * mean) * (1.0f / 511.0f);  // ddof=1
    const float rstd = rsqrtf(var + 1e-5f);
    const float gg = g1[s], be = b1[s];

    float v[4];
#pragma unroll
    for (int j = 0; j < 4; j++) v[j] = gg * (act[j] - mean) * rstd + be;
    const size_t pr = ((size_t)bs << 8) + (t << 1);
    *(uint2*)(n1o + pr) = make_uint2(h2pk(v[0], v[1]), h2pk(v[2], v[3]));
}

// ---------------- FP16 GEMM-NT, ldmatrix fragment loads ----------------------
// C[m,e] = sum_d A[m,d]*B[e,d].  M=16384, N=K=512, 128x128 tile, k-tile 16.
// mode 0: C = acc + ts_emb[te[b],e]   -> packed C0
// mode 4: z=0: Q=acc*0.125 -> C0; z=1: K -> C1; z=2: V -> C2   (packed)
// mode 3: Cf = acc + bo[e] + conv[m,e]  (fp32)
#define SP2 12               // smem row stride in pairs (8 data + 4 pad)
#define GARR 1536            // words per array per stage (128*12)
#define GST  (2*GARR)        // 3072 words per stage (A, B)
__global__ __launch_bounds__(256, 2) void fp16_gemm(
    const unsigned* __restrict__ Ag,
    const unsigned* __restrict__ B0, const unsigned* __restrict__ B1,
    const unsigned* __restrict__ B2,
    unsigned* __restrict__ C0, unsigned* __restrict__ C1, unsigned* __restrict__ C2,
    float* __restrict__ Cf, int mode, const int* __restrict__ te,
    const float* __restrict__ aux1, const float* __restrict__ aux2)
{
    __shared__ unsigned gsm[2 * GST];            // 24576 B static

    const unsigned* Bg = B0;
    unsigned* C = C0;
    float scale = 1.0f;
    if (mode == 4) {
        if (blockIdx.z == 1)      { Bg = B1; C = C1; }
        else if (blockIdx.z == 2) { Bg = B2; C = C2; }
        else                      { scale = 0.125f; }
    }

    const int t = threadIdx.x;
    const int row0 = blockIdx.y << 7, col0 = blockIdx.x << 7;
    const int lrow = t >> 1, lchunk = t & 1;
    const size_t aoff = ((size_t)(row0 + lrow) << 8) + (lchunk << 2);
    const size_t boff = ((size_t)(col0 + lrow) << 8) + (lchunk << 2);
    const unsigned cta = su32(gsm);
    const unsigned sbase = cta + (unsigned)((lrow * SP2 + (lchunk << 2)) << 2);

    const int warp = t >> 5, lane = t & 31;
    const int gid = lane >> 2, tig = lane & 3;
    const int wm = warp & 1, wn = warp >> 1;

    const int arowr = (wm << 6) + (lane & 15);
    const unsigned acolB = (unsigned)(lane & 16);
    const int browr = (wn << 5) + (lane & 7) + (((lane >> 4) & 1) << 3);
    const unsigned bcolB = (unsigned)(((lane >> 3) & 1) << 4);

    float acc[4][4][4];
#pragma unroll
    for (int mt = 0; mt < 4; mt++)
#pragma unroll
        for (int nt = 0; nt < 4; nt++)
#pragma unroll
            for (int r = 0; r < 4; r++) acc[mt][nt][r] = 0.f;

#define GLOAD(kt, st) do {                                   \
        const unsigned kc = (unsigned)(kt) << 3;             \
        const unsigned sd = sbase + (st) * (GST << 2);       \
        CP16(sd,               Ag + aoff + kc);              \
        CP16(sd + (GARR << 2), Bg + boff + kc);              \
    } while (0)

    GLOAD(0, 0); CP_COMMIT();
    GLOAD(1, 1); CP_COMMIT();

    for (int kt = 0; kt < 32; kt++) {
        CP_WAIT1();
        __syncthreads();
        const unsigned stB = cta + (kt & 1) * (GST << 2);

        unsigned bh[4][2];
#pragma unroll
        for (int ntp = 0; ntp < 2; ntp++) {
            const unsigned ba = stB +
                ((GARR + (browr + (ntp << 4)) * SP2) << 2) + bcolB;
            ldsm_x4(bh[2*ntp][0], bh[2*ntp][1], bh[2*ntp+1][0], bh[2*ntp+1][1], ba);
        }
#pragma unroll
        for (int mt = 0; mt < 4; mt++) {
            const unsigned aa = stB + (((arowr + (mt << 4)) * SP2) << 2) + acolB;
            unsigned a[4];
            ldsm_x4(a[0], a[1], a[2], a[3], aa);
#pragma unroll
            for (int nt = 0; nt < 4; nt++)
                mma16(acc[mt][nt], a, bh[nt]);
        }
        __syncthreads();
        if (kt + 2 < 32) GLOAD(kt + 2, kt & 1);
        CP_COMMIT();
    }

    // ---- epilogue ----
    if (mode == 3) {
#pragma unroll
        for (int mt = 0; mt < 4; mt++) {
            const int r1 = row0 + (wm << 6) + (mt << 4) + gid;
            const int r2 = r1 + 8;
#pragma unroll
            for (int nt = 0; nt < 4; nt++) {
                const int c = col0 + (wn << 5) + (nt << 3) + (tig << 1);
                const float a0 = aux1[c], a1 = aux1[c + 1];
                float v0 = acc[mt][nt][0] + a0 + aux2[((size_t)r1 << 9) + c];
                float v1 = acc[mt][nt][1] + a1 + aux2[((size_t)r1 << 9) + c + 1];
                float v2 = acc[mt][nt][2] + a0 + aux2[((size_t)r2 << 9) + c];
                float v3 = acc[mt][nt][3] + a1 + aux2[((size_t)r2 << 9) + c + 1];
                *(float2*)(Cf + ((size_t)r1 << 9) + c) = make_float2(v0, v1);
                *(float2*)(Cf + ((size_t)r2 << 9) + c) = make_float2(v2, v3);
            }
        }
    } else {
        int e = 0;
        if (mode == 0) e = te[row0 >> 10];
#pragma unroll
        for (int mt = 0; mt < 4; mt++) {
            const int r1 = row0 + (wm << 6) + (mt << 4) + gid;
            const int r2 = r1 + 8;
#pragma unroll
            for (int nt = 0; nt < 4; nt++) {
                const int c = col0 + (wn << 5) + (nt << 3) + (tig << 1);
                float a0 = 0.f, a1 = 0.f;
                if (mode == 0) {
                    a0 = aux1[((size_t)e << 9) + c];
                    a1 = aux1[((size_t)e << 9) + c + 1];
                }
                const float v0 = acc[mt][nt][0] * scale + a0;
                const float v1 = acc[mt][nt][1] * scale + a1;
                const float v2 = acc[mt][nt][2] * scale + a0;
                const float v3 = acc[mt][nt][3] * scale + a1;
                C[((size_t)r1 << 8) + (c >> 1)] = h2pk(v0, v1);
                C[((size_t)r2 << 8) + (c >> 1)] = h2pk(v2, v3);
            }
        }
    }
}

// ---------------- FA2-style fp16 attention, static 18KB smem -----------------
// out[j] = sum_{i<=j} softmax_i(k_j . q_i) v_i   (Q pre-scaled)
// 64 j rows resident (4 warps x 16); i streamed in 32-row tiles, double-buffered.
// K fragments direct from global; Q ldmatrix; V ldmatrix.trans; P in registers.
// Stage layout (words): QS 0 | VS 1152 ; stage size 2304.
#define RS 36
#define STW 2304
__global__ __launch_bounds__(128, 4) void k_attn6(
    const unsigned* __restrict__ q, const unsigned* __restrict__ k,
    const unsigned* __restrict__ v, unsigned* __restrict__ ao)
{
    __shared__ unsigned smw[2 * STW];            // 18432 B static

    const int jt = (gridDim.x - 1) - blockIdx.x; // big tiles first
    const int h = blockIdx.y, b = blockIdx.z;
    const int j0 = jt << 6;
    const int t = threadIdx.x, warp = t >> 5, lane = t & 31;
    const int gid = lane >> 2, tig = lane & 3;
    const size_t rowb = ((size_t)b << 10);
    const int coff2 = h << 5;
    const unsigned sbase = su32(smw);

    const int lrow = t >> 2;                     // 0..31
    const int lsub = (t & 3) << 3;               // word offset 0,8,16,24

#define LOADQV(i0_, st_) do {                                                   \
        const size_t g_ = ((rowb + (unsigned)(i0_) + lrow) << 8) + coff2 + lsub; \
        const unsigned s_ = sbase + (((st_) * STW + lrow * RS + lsub) << 2);     \
        CP16(s_,                   q + g_);                                     \
        CP16(s_ + 16,              q + g_ + 4);                                 \
        CP16(s_ + (1152 << 2),     v + g_);                                     \
        CP16(s_ + (1152 << 2) + 16, v + g_ + 4);                                \
    } while (0)

    const int ntiles = (jt << 1) + 2;

    LOADQV(0, 0); CP_COMMIT();
    if (ntiles > 1) LOADQV(32, 1);
    CP_COMMIT();

    // K fragments direct from global (A-operand layout)
    const int krow = j0 + (warp << 4) + gid;
    const size_t kg0 = ((rowb + krow) << 8) + coff2;
    const size_t kg8 = ((rowb + krow + 8) << 8) + coff2;
    unsigned kf[4][4];
#pragma unroll
    for (int ks = 0; ks < 4; ks++) {
        const int p = (ks << 3) + tig;
        kf[ks][0] = k[kg0 + p];     kf[ks][1] = k[kg8 + p];
        kf[ks][2] = k[kg0 + p + 4]; kf[ks][3] = k[kg8 + p + 4];
    }

    const int qrowrel = (lane & 7) + ((lane & 16) >> 1);
    const unsigned qcol = (lane & 8) >> 1;
    const int vrowrel = (lane & 7) + (lane & 8);
    const unsigned vcol = (lane & 16) >> 2;

    float m0 = NEGF, m1 = NEGF, l0 = 0.f, l1 = 0.f;
    float acc[8][4];
#pragma unroll
    for (int nb = 0; nb < 8; nb++)
#pragma unroll
        for (int r = 0; r < 4; r++) acc[nb][r] = 0.f;

    const int jr0 = j0 + (warp << 4) + gid, jr1 = jr0 + 8;

    for (int it = 0; it < ntiles; ++it) {
        CP_WAIT1();
        __syncthreads();
        const unsigned stw = (it & 1) * STW;

        // ---- scores: m=j(16/warp), n=i(32), k=c(64) ----
        float s[4][4];
#pragma unroll
        for (int nb = 0; nb < 4; nb++)
#pragma unroll
            for (int r = 0; r < 4; r++) s[nb][r] = 0.f;
#pragma unroll
        for (int ks = 0; ks < 4; ks++) {
            unsigned qb[4][2];
#pragma unroll
            for (int nbp = 0; nbp < 2; nbp++) {
                const unsigned qa = sbase +
                    ((stw + ((nbp << 4) + qrowrel) * RS + (ks << 3) + qcol) << 2);
                unsigned q0, q1, q2, q3;
                ldsm_x4(q0, q1, q2, q3, qa);
                qb[2*nbp][0] = q0; qb[2*nbp][1] = q1;
                qb[2*nbp+1][0] = q2; qb[2*nbp+1][1] = q3;
            }
#pragma unroll
            for (int u = 0; u < 4; u++) mma16(s[u], kf[ks], qb[u]);
        }

        // ---- causal mask (last two tiles) ----
        if (it >= ntiles - 2) {
            const int i0 = it << 5;
#pragma unroll
            for (int nb = 0; nb < 4; nb++) {
                const int c = i0 + (nb << 3) + (tig << 1);
                if (c     > jr0) s[nb][0] = NEGF;
                if (c + 1 > jr0) s[nb][1] = NEGF;
                if (c     > jr1) s[nb][2] = NEGF;
                if (c + 1 > jr1) s[nb][3] = NEGF;
            }
        }

        // ---- online softmax (rows jr0, jr1) ----
        float mt0 = NEGF, mt1 = NEGF;
#pragma unroll
        for (int nb = 0; nb < 4; nb++) {
            mt0 = fmaxf(mt0, fmaxf(s[nb][0], s[nb][1]));
            mt1 = fmaxf(mt1, fmaxf(s[nb][2], s[nb][3]));
        }
        mt0 = fmaxf(mt0, __shfl_xor_sync(0xffffffffu, mt0, 1));
        mt0 = fmaxf(mt0, __shfl_xor_sync(0xffffffffu, mt0, 2));
        mt1 = fmaxf(mt1, __shfl_xor_sync(0xffffffffu, mt1, 1));
        mt1 = fmaxf(mt1, __shfl_xor_sync(0xffffffffu, mt1, 2));
        const float mn0 = fmaxf(m0, mt0), mn1 = fmaxf(m1, mt1);
        const float sc0 = __expf(m0 - mn0), sc1 = __expf(m1 - mn1);
        m0 = mn0; m1 = mn1;

        float rs0 = 0.f, rs1 = 0.f;
#pragma unroll
        for (int nb = 0; nb < 4; nb++) {
            s[nb][0] = __expf(s[nb][0] - mn0);
            s[nb][1] = __expf(s[nb][1] - mn0);
            s[nb][2] = __expf(s[nb][2] - mn1);
            s[nb][3] = __expf(s[nb][3] - mn1);
            rs0 += s[nb][0] + s[nb][1];
            rs1 += s[nb][2] + s[nb][3];
        }
        rs0 += __shfl_xor_sync(0xffffffffu, rs0, 1);
        rs0 += __shfl_xor_sync(0xffffffffu, rs0, 2);
        rs1 += __shfl_xor_sync(0xffffffffu, rs1, 1);
        rs1 += __shfl_xor_sync(0xffffffffu, rs1, 2);
        l0 = l0 * sc0 + rs0;
        l1 = l1 * sc1 + rs1;

#pragma unroll
        for (int nb = 0; nb < 8; nb++) {
            acc[nb][0] *= sc0; acc[nb][1] *= sc0;
            acc[nb][2] *= sc1; acc[nb][3] *= sc1;
        }

        // ---- PV: m=j(16/warp), n=c(64), k=i(32); P from registers ----
#pragma unroll
        for (int kk = 0; kk < 2; kk++) {
            unsigned pa[4];
            pa[0] = h2pk(s[2*kk][0],     s[2*kk][1]);
            pa[1] = h2pk(s[2*kk][2],     s[2*kk][3]);
            pa[2] = h2pk(s[2*kk + 1][0], s[2*kk + 1][1]);
            pa[3] = h2pk(s[2*kk + 1][2], s[2*kk + 1][3]);
#pragma unroll
            for (int nbp = 0; nbp < 4; nbp++) {
                const unsigned va = sbase +
                    ((stw + 1152 + ((kk << 4) + vrowrel) * RS + (nbp << 3) + vcol) << 2);
                unsigned v0, v1, v2, v3;
                ldsm_x4t(v0, v1, v2, v3, va);
                unsigned vb0[2] = {v0, v1}, vb1[2] = {v2, v3};
                mma16(acc[2*nbp],     pa, vb0);
                mma16(acc[2*nbp + 1], pa, vb1);
            }
        }

        __syncthreads();
        if (it + 2 < ntiles) LOADQV((it + 2) << 5, it & 1);
        CP_COMMIT();
    }

    // ---- epilogue: /l, pack, store ----
    const float rl0 = 1.0f / l0, rl1 = 1.0f / l1;
    const size_t o1 = ((rowb + jr0) << 8) + coff2;
    const size_t o2 = ((rowb + jr1) << 8) + coff2;
#pragma unroll
    for (int nb = 0; nb < 8; nb++) {
        const int pp = (nb << 2) + tig;
        ao[o1 + pp] = h2pk(acc[nb][0] * rl0, acc[nb][1] * rl0);
        ao[o2 + pp] = h2pk(acc[nb][2] * rl1, acc[nb][3] * rl1);
    }
#undef LOADQV
}

// ---------------- kernel 4: LN2 + coalesced transpose to (B,D,S) -------------
__global__ __launch_bounds__(256) void k_ln2t(
    const float* __restrict__ res, const float* __restrict__ g2,
    const float* __restrict__ b2, float* __restrict__ out)
{
    __shared__ float sm[16 * 513];
    __shared__ float smean[16], srstd[16];

    const int blk = blockIdx.x;
    const int b = blk >> 6, s0 = (blk & 63) << 4;
    const int t = threadIdx.x;

    for (int i = t; i < 2048; i += 256) {
        const int r = i >> 7, c4 = (i & 127) << 2;
        const float4 v = *(const float4*)(res + ((size_t)((b << 10) + s0 + r) << 9) + c4);
        float* d = sm + r * 513 + c4;
        d[0] = v.x; d[1] = v.y; d[2] = v.z; d[3] = v.w;
    }
    __syncthreads();

    {
        const int r = t >> 4, tr = t & 15;
        float s1 = 0.f, s2 = 0.f;
        for (int kx = tr; kx < 512; kx += 16) {
            const float x = sm[r * 513 + kx];
            s1 += x; s2 += x * x;
        }
#pragma unroll
        for (int o = 8; o; o >>= 1) {
            s1 += __shfl_down_sync(0xffffffffu, s1, o, 16);
            s2 += __shfl_down_sync(0xffffffffu, s2, o, 16);
        }
        if (tr == 0) {
            const float mean = s1 * (1.0f / 512.0f);
            const float var  = (s2 - 512.0f * mean * mean) * (1.0f / 511.0f);
            smean[r] = mean;
            srstd[r] = rsqrtf(var + 1e-5f);
        }
    }
    __syncthreads();

    const float gg = g2[s0 + (t & 15)], be = b2[s0 + (t & 15)];
    for (int i = t; i < 8192; i += 256) {
        const int d = i >> 4, si = i & 15;
        const float x = sm[si * 513 + d];
        out[((size_t)((b << 9) + d) << 10) + s0 + si] =
            gg * (x - smean[si]) * srstd[si] + be;
    }
}

// ---------------- launch -----------------------------------------------------
extern "C" void kernel_launch(void* const* d_in, const int* in_sizes, int n_in,
                              void* d_out, int out_size)
{
    const float* ts     = (const float*)d_in[0];
    const int*   te     = (const int*)  d_in[1];
    const float* conv_w = (const float*)d_in[2];
    const float* conv_b = (const float*)d_in[3];
    const float* pe     = (const float*)d_in[4];
    const float* ts_emb = (const float*)d_in[5];
    const float* g1     = (const float*)d_in[6];
    const float* b1     = (const float*)d_in[7];
    const float* Mw     = (const float*)d_in[8];
    const float* Wq     = (const float*)d_in[9];
    const float* Wk     = (const float*)d_in[10];
    const float* Wv     = (const float*)d_in[11];
    const float* Wo     = (const float*)d_in[12];
    const float* bo     = (const float*)d_in[13];
    const float* g2     = (const float*)d_in[14];
    const float* b2     = (const float*)d_in[15];
    float* out = (float*)d_out;

    float *pc, *pr;
    unsigned *pn1, *pd, *pq, *pk, *pv, *pa;
    unsigned *wm, *wq, *wk, *wv, *wo;
    cudaGetSymbolAddress((void**)&pc,  g_conv);
    cudaGetSymbolAddress((void**)&pr,  g_res);
    cudaGetSymbolAddress((void**)&pn1, g_n1);
    cudaGetSymbolAddress((void**)&pd,  g_d);
    cudaGetSymbolAddress((void**)&pq,  g_q);
    cudaGetSymbolAddress((void**)&pk,  g_k);
    cudaGetSymbolAddress((void**)&pv,  g_v);
    cudaGetSymbolAddress((void**)&pa,  g_a);
    cudaGetSymbolAddress((void**)&wm,  g_wm);
    cudaGetSymbolAddress((void**)&wq,  g_wq);
    cudaGetSymbolAddress((void**)&wk,  g_wk);
    cudaGetSymbolAddress((void**)&wv,  g_wv);
    cudaGetSymbolAddress((void**)&wo,  g_wo);

    // weight packing (once per launch)
    const int n4 = DDIM * DDIM / 4;
    CvtTab tab;
    tab.in[0] = (const float4*)Mw; tab.o[0] = (uint2*)wm;
    tab.in[1] = (const float4*)Wq; tab.o[1] = (uint2*)wq;
    tab.in[2] = (const float4*)Wk; tab.o[2] = (uint2*)wk;
    tab.in[3] = (const float4*)Wv; tab.o[3] = (uint2*)wv;
    tab.in[4] = (const float4*)Wo; tab.o[4] = (uint2*)wo;
    k_cvt5<<<dim3(n4 / 256, 5), 256>>>(tab, n4);

    k_embed<<<BSN, 128>>>(ts, conv_w, conv_b, pe, g1, b1, pc, pn1);

    dim3 gg(4, 128, 1);
    // dense = M @ n1 + ts_emb gather -> packed fp16
    fp16_gemm<<<gg, 256>>>(pn1, wm, nullptr, nullptr,
                           pd, nullptr, nullptr,
                           nullptr, 0, te, ts_emb, nullptr);
    // fused QKV (z=0: Q*0.125, z=1: K, z=2: V) -> packed fp16
    dim3 gq(4, 128, 3);
    fp16_gemm<<<gq, 256>>>(pd, wq, wk, wv,
                           pq, pk, pv,
                           nullptr, 4, nullptr, nullptr, nullptr);

    k_attn6<<<dim3(SSZ / 64, 8, BB), 128>>>(pq, pk, pv, pa);

    // res = Wo @ attn + bo + conv residual (fp32)
    fp16_gemm<<<gg, 256>>>(pa, wo, nullptr, nullptr,
                           nullptr, nullptr, nullptr,
                           pr, 3, nullptr, bo, pc);

    k_ln2t<<<BB * 64, 256>>>(pr, g2, b2, out);
}